// round 14
// baseline (speedup 1.0000x reference)
#include <cuda_runtime.h>
#include <cuda_bf16.h>
#include <cstdint>

#define N_NODES 50000
#define N_EDGES 600000
#define HID     128
#define N_GRAPHS 32
#define D_OUT   3
#define SCAN_BLOCKS ((N_NODES + 255) / 256)   // 196

typedef unsigned long long u64;

// ---------------- scratch (device globals; no allocs) ----------------
__device__ int   g_cnt[N_NODES];
__device__ int   g_rowptr[N_NODES + 1];
__device__ int   g_cursor[N_NODES];
__device__ int   g_col[N_EDGES];
__device__ int   g_bsum[SCAN_BLOCKS];
__device__ int   g_tick;
__device__ __nv_bfloat16 g_P [(size_t)N_NODES * HID];  // conv0 messages
__device__ __nv_bfloat16 g_P2[(size_t)N_NODES * HID];  // conv1 messages
__device__ float g_bufA[(size_t)N_NODES * HID];        // partial (reused)
__device__ float g_gsum[N_GRAPHS * HID];
__device__ float g_gcnt[N_GRAPHS];

// ---------------- f32x2 helpers ----------------
__device__ __forceinline__ u64 pack_dup(float a) {
    u64 r;
    asm("mov.b64 %0, {%1,%1};" : "=l"(r) : "f"(a));
    return r;
}
__device__ __forceinline__ float2 unpack2(u64 v) {
    float2 r;
    asm("mov.b64 {%0,%1}, %2;" : "=f"(r.x), "=f"(r.y) : "l"(v));
    return r;
}
__device__ __forceinline__ void ffma2(u64& acc, u64 a, u64 b) {
    asm("fma.rn.f32x2 %0, %1, %2, %0;" : "+l"(acc) : "l"(a), "l"(b));
}

// ---- gather one node's mean message + partial + relu (float4 per lane) ----
__device__ __forceinline__ float4 agg_node(const __nv_bfloat16* __restrict__ P,
                                           const float* __restrict__ partial,
                                           int node, int lane) {
    int s = g_rowptr[node];
    int e = g_rowptr[node + 1];
    float4 acc = make_float4(0.f, 0.f, 0.f, 0.f);
    for (int j = s; j < e; j++) {
        int sn = g_col[j];
        uint2 v = *((const uint2*)(P + (size_t)sn * HID) + lane);
        float2 f0 = __bfloat1622float2(*reinterpret_cast<__nv_bfloat162*>(&v.x));
        float2 f1 = __bfloat1622float2(*reinterpret_cast<__nv_bfloat162*>(&v.y));
        acc.x += f0.x; acc.y += f0.y; acc.z += f1.x; acc.w += f1.y;
    }
    int deg = e - s;
    float inv = 1.0f / (float)(deg > 0 ? deg : 1);
    float4 p = *(const float4*)(partial + (size_t)node * HID + lane * 4);
    float4 o;
    o.x = fmaxf(p.x + acc.x * inv, 0.f);
    o.y = fmaxf(p.y + acc.y * inv, 0.f);
    o.z = fmaxf(p.z + acc.z * inv, 0.f);
    o.w = fmaxf(p.w + acc.w * inv, 0.f);
    return o;
}

// ---- R7-proven staging helpers (256 threads) ----
__device__ __forceinline__ void stage_A(float* sIn, const float* __restrict__ A,
                                        int m0, int M, int lane, int sub) {
    #pragma unroll
    for (int it = 0; it < 16; it++) {
        int row = it * 8 + sub;
        int grow = m0 + row;
        float4 v = make_float4(0.f, 0.f, 0.f, 0.f);
        if (grow < M) v = *(const float4*)(A + (size_t)grow * 128 + lane * 4);
        *(float4*)(sIn + row * 128 + lane * 4) = v;
    }
}
// sW k-major, float4 XOR-swizzle: (k, c4) at k*128 + ((c4 ^ ((k>>2)&31))<<2)
__device__ __forceinline__ void stage_W(float* sW, const float* __restrict__ W,
                                        int lane, int sub) {
    #pragma unroll
    for (int it = 0; it < 16; it++) {
        int col = it * 8 + sub;
        int c4 = col >> 2, cl = col & 3;
        float4 v = *(const float4*)(W + col * 128 + (lane << 2));
        float vv[4] = {v.x, v.y, v.z, v.w};
        #pragma unroll
        for (int i = 0; i < 4; i++) {
            int k = (lane << 2) + i;     // (k>>2)&31 == lane
            sW[k * 128 + ((c4 ^ lane) << 2) + cl] = vv[i];
        }
    }
}

// ---- R7-proven FFMA2 k-loops ----
__device__ __forceinline__ void kloop_single(const float* sIn, const float* sW1,
                                             u64 acc1[8][4], int tx, int ty) {
    #pragma unroll 4
    for (int k = 0; k < 128; k++) {
        u64 a2[8];
        #pragma unroll
        for (int r = 0; r < 8; r++)
            a2[r] = pack_dup(sIn[(ty * 8 + r) * 128 + k]);
        int swz = (k >> 2) & 31;
        const float* w1r = sW1 + k * 128;
        ulonglong2 p0 = *(const ulonglong2*)(w1r + ((((tx << 1)    ) ^ swz) << 2));
        ulonglong2 p1 = *(const ulonglong2*)(w1r + ((((tx << 1) | 1) ^ swz) << 2));
        u64 b1v[4] = {p0.x, p0.y, p1.x, p1.y};
        #pragma unroll
        for (int r = 0; r < 8; r++)
            #pragma unroll
            for (int c = 0; c < 4; c++)
                ffma2(acc1[r][c], a2[r], b1v[c]);
    }
}
__device__ __forceinline__ void kloop_dual(const float* sIn, const float* sW1,
                                           const float* sW2,
                                           u64 acc1[8][4], u64 acc2[8][4],
                                           int tx, int ty) {
    #pragma unroll 4
    for (int k = 0; k < 128; k++) {
        u64 a2[8];
        #pragma unroll
        for (int r = 0; r < 8; r++)
            a2[r] = pack_dup(sIn[(ty * 8 + r) * 128 + k]);
        int swz = (k >> 2) & 31;
        const float* w1r = sW1 + k * 128;
        ulonglong2 p0 = *(const ulonglong2*)(w1r + ((((tx << 1)    ) ^ swz) << 2));
        ulonglong2 p1 = *(const ulonglong2*)(w1r + ((((tx << 1) | 1) ^ swz) << 2));
        u64 b1v[4] = {p0.x, p0.y, p1.x, p1.y};
        #pragma unroll
        for (int r = 0; r < 8; r++)
            #pragma unroll
            for (int c = 0; c < 4; c++)
                ffma2(acc1[r][c], a2[r], b1v[c]);
        const float* w2r = sW2 + k * 128;
        ulonglong2 q0 = *(const ulonglong2*)(w2r + ((((tx << 1)    ) ^ swz) << 2));
        ulonglong2 q1 = *(const ulonglong2*)(w2r + ((((tx << 1) | 1) ^ swz) << 2));
        u64 b2v[4] = {q0.x, q0.y, q1.x, q1.y};
        #pragma unroll
        for (int r = 0; r < 8; r++)
            #pragma unroll
            for (int c = 0; c < 4; c++)
                ffma2(acc2[r][c], a2[r], b2v[c]);
    }
}

// ---- dual epilogue: out1 fp32 (+bias), out2 bf16 ----
__device__ __forceinline__ void epi_dual(u64 acc1[8][4], u64 acc2[8][4],
                                         const float* __restrict__ bias,
                                         float* __restrict__ out1,
                                         __nv_bfloat16* __restrict__ out2,
                                         int m0, int M, int tx, int ty) {
    float bv[8];
    #pragma unroll
    for (int j = 0; j < 8; j++) bv[j] = bias[tx * 8 + j];
    #pragma unroll
    for (int r = 0; r < 8; r++) {
        int grow = m0 + ty * 8 + r;
        if (grow < M) {
            float o[8];
            #pragma unroll
            for (int c = 0; c < 4; c++) {
                float2 v = unpack2(acc1[r][c]);
                o[2 * c]     = v.x + bv[2 * c];
                o[2 * c + 1] = v.y + bv[2 * c + 1];
            }
            float4* d1 = (float4*)(out1 + (size_t)grow * 128 + tx * 8);
            d1[0] = make_float4(o[0], o[1], o[2], o[3]);
            d1[1] = make_float4(o[4], o[5], o[6], o[7]);
            __nv_bfloat162 h[4];
            #pragma unroll
            for (int c = 0; c < 4; c++) {
                float2 v = unpack2(acc2[r][c]);
                h[c] = __float22bfloat162_rn(v);
            }
            uint4 pk;
            pk.x = *(uint32_t*)&h[0];
            pk.y = *(uint32_t*)&h[1];
            pk.z = *(uint32_t*)&h[2];
            pk.w = *(uint32_t*)&h[3];
            *(uint4*)(out2 + (size_t)grow * 128 + tx * 8) = pk;
        }
    }
}

// =================================================================
// conv0 dual GEMM (exact R13): out1 = A@W1^T+bias [fp32], out2 = bf16(A@W2^T)
// =================================================================
__global__ void __launch_bounds__(256, 1)
gemm_dual(const float* __restrict__ A,
          const float* __restrict__ W1, const float* __restrict__ W2,
          const float* __restrict__ bias,
          float* __restrict__ out1, __nv_bfloat16* __restrict__ out2, int M) {
    extern __shared__ float smem[];
    float* sIn = smem;
    float* sW1 = smem + 16384;
    float* sW2 = smem + 32768;

    int tid = threadIdx.x;
    int tx = tid & 15, ty = tid >> 4;
    int lane = tid & 31, sub = tid >> 5;
    int m0 = blockIdx.x * 128;

    stage_A(sIn, A, m0, M, lane, sub);
    stage_W(sW1, W1, lane, sub);
    stage_W(sW2, W2, lane, sub);
    __syncthreads();

    u64 acc1[8][4], acc2[8][4];
    #pragma unroll
    for (int r = 0; r < 8; r++)
        #pragma unroll
        for (int c = 0; c < 4; c++) { acc1[r][c] = 0ull; acc2[r][c] = 0ull; }

    kloop_dual(sIn, sW1, sW2, acc1, acc2, tx, ty);
    epi_dual(acc1, acc2, bias, out1, out2, m0, M, tx, ty);
}

// =================================================================
// fused conv0-combine + lin1 + conv1:
//   prologue: sIn[row] = relu(partial[row] + mean_{nbr} P[nbr])  (gather)
//   phase 1:  h = relu(sIn@W1^T + b1) -> sIn
//   phase 2:  out1 = h@Wr^T + blr [fp32], out2 = bf16(h@Wl^T)
// Reads bufA (own rows only) before writing them; writes messages to P2.
// =================================================================
__global__ void __launch_bounds__(256, 1)
gemm_fused_agg(const __nv_bfloat16* __restrict__ P,
               const float* __restrict__ partial,
               const float* __restrict__ W1, const float* __restrict__ b1,
               const float* __restrict__ Wr, const float* __restrict__ Wl,
               const float* __restrict__ blr,
               float* __restrict__ out1, __nv_bfloat16* __restrict__ out2,
               int M) {
    extern __shared__ float smem[];
    float* sIn = smem;
    float* sW1 = smem + 16384;
    float* sW2 = smem + 32768;

    int tid = threadIdx.x;
    int tx = tid & 15, ty = tid >> 4;
    int lane = tid & 31, sub = tid >> 5;
    int m0 = blockIdx.x * 128;

    // ---- prologue: conv0 combine straight into sIn ----
    #pragma unroll 1
    for (int it = 0; it < 16; it++) {
        int row = it * 8 + sub;
        int node = m0 + row;
        float4 o = make_float4(0.f, 0.f, 0.f, 0.f);
        if (node < M) o = agg_node(P, partial, node, lane);
        *(float4*)(sIn + row * 128 + lane * 4) = o;
    }
    stage_W(sW1, W1, lane, sub);
    __syncthreads();

    // ---- phase 1: lin1 ----
    u64 acc1[8][4], acc2[8][4];
    #pragma unroll
    for (int r = 0; r < 8; r++)
        #pragma unroll
        for (int c = 0; c < 4; c++) acc1[r][c] = 0ull;

    kloop_single(sIn, sW1, acc1, tx, ty);
    __syncthreads();   // everyone's reads of sIn / sW1 complete

    // write h = relu(acc1 + b1) back into sIn (same row-major layout)
    {
        float bv1[8];
        #pragma unroll
        for (int j = 0; j < 8; j++) bv1[j] = b1[tx * 8 + j];
        #pragma unroll
        for (int r = 0; r < 8; r++) {
            float o[8];
            #pragma unroll
            for (int c = 0; c < 4; c++) {
                float2 v = unpack2(acc1[r][c]);
                o[2 * c]     = fmaxf(v.x + bv1[2 * c], 0.f);
                o[2 * c + 1] = fmaxf(v.y + bv1[2 * c + 1], 0.f);
            }
            float4* d = (float4*)(sIn + (ty * 8 + r) * 128 + tx * 8);
            d[0] = make_float4(o[0], o[1], o[2], o[3]);
            d[1] = make_float4(o[4], o[5], o[6], o[7]);
        }
    }
    stage_W(sW1, Wr, lane, sub);
    stage_W(sW2, Wl, lane, sub);
    __syncthreads();

    // ---- phase 2: conv1 dual from h ----
    #pragma unroll
    for (int r = 0; r < 8; r++)
        #pragma unroll
        for (int c = 0; c < 4; c++) { acc1[r][c] = 0ull; acc2[r][c] = 0ull; }

    kloop_dual(sIn, sW1, sW2, acc1, acc2, tx, ty);
    epi_dual(acc1, acc2, blr, out1, out2, m0, M, tx, ty);
}

// ---------------- CSR build ----------------
__global__ void zero_kernel() {
    int i = blockIdx.x * blockDim.x + threadIdx.x;
    if (i < N_NODES) g_cnt[i] = 0;
    if (i < N_GRAPHS * HID) g_gsum[i] = 0.0f;
    if (i < N_GRAPHS) g_gcnt[i] = 0.0f;
    if (i == 0) g_tick = 0;
}

__global__ void hist_kernel(const int* __restrict__ dst) {
    int e4 = blockIdx.x * blockDim.x + threadIdx.x;
    if (e4 < N_EDGES / 4) {
        int4 d = ((const int4*)dst)[e4];
        atomicAdd(&g_cnt[d.x], 1);
        atomicAdd(&g_cnt[d.y], 1);
        atomicAdd(&g_cnt[d.z], 1);
        atomicAdd(&g_cnt[d.w], 1);
    }
}

__global__ void scan1_kernel() {
    __shared__ int ws[8];
    int tid = threadIdx.x, lane = tid & 31, w = tid >> 5;
    int i = blockIdx.x * 256 + tid;
    int v = (i < N_NODES) ? g_cnt[i] : 0;
    #pragma unroll
    for (int off = 16; off > 0; off >>= 1)
        v += __shfl_down_sync(0xffffffffu, v, off);
    if (lane == 0) ws[w] = v;
    __syncthreads();
    if (tid == 0) {
        int s = 0;
        #pragma unroll
        for (int j = 0; j < 8; j++) s += ws[j];
        g_bsum[blockIdx.x] = s;
    }
}

__global__ void scan3m_kernel() {
    __shared__ int ws[8];
    __shared__ int s_boff;
    int tid = threadIdx.x, lane = tid & 31, w = tid >> 5;

    int v = (tid < SCAN_BLOCKS) ? g_bsum[tid] : 0;
    int x = v;
    #pragma unroll
    for (int off = 1; off < 32; off <<= 1) {
        int t = __shfl_up_sync(0xffffffffu, x, off);
        if (lane >= off) x += t;
    }
    if (lane == 31) ws[w] = x;
    __syncthreads();
    if (w == 0 && lane < 8) {
        int y = ws[lane];
        #pragma unroll
        for (int off = 1; off < 8; off <<= 1) {
            int t = __shfl_up_sync(0xffu, y, off);
            if (lane >= off) y += t;
        }
        ws[lane] = y;
    }
    __syncthreads();
    int incl = x + (w > 0 ? ws[w - 1] : 0);
    if (tid == blockIdx.x) s_boff = incl - v;
    if (blockIdx.x == 0 && tid == 0) g_rowptr[0] = 0;
    __syncthreads();

    int i = blockIdx.x * 256 + tid;
    int c = (i < N_NODES) ? g_cnt[i] : 0;
    int y = c;
    #pragma unroll
    for (int off = 1; off < 32; off <<= 1) {
        int t = __shfl_up_sync(0xffffffffu, y, off);
        if (lane >= off) y += t;
    }
    if (lane == 31) ws[w] = y;
    __syncthreads();
    if (w == 0 && lane < 8) {
        int z = ws[lane];
        #pragma unroll
        for (int off = 1; off < 8; off <<= 1) {
            int t = __shfl_up_sync(0xffu, z, off);
            if (lane >= off) z += t;
        }
        ws[lane] = z;
    }
    __syncthreads();
    int inc2 = y + (w > 0 ? ws[w - 1] : 0) + s_boff;
    if (i < N_NODES) {
        g_rowptr[i + 1] = inc2;
        g_cursor[i] = inc2 - c;
    }
}

__global__ void fill_kernel(const int* __restrict__ src,
                            const int* __restrict__ dst) {
    int e4 = blockIdx.x * blockDim.x + threadIdx.x;
    if (e4 < N_EDGES / 4) {
        int4 d = ((const int4*)dst)[e4];
        int4 s = ((const int4*)src)[e4];
        g_col[atomicAdd(&g_cursor[d.x], 1)] = s.x;
        g_col[atomicAdd(&g_cursor[d.y], 1)] = s.y;
        g_col[atomicAdd(&g_cursor[d.z], 1)] = s.z;
        g_col[atomicAdd(&g_cursor[d.w], 1)] = s.w;
    }
}

// =================================================================
// fused conv1-combine + global mean pool + final fc (ticketed):
// warp-per-node gather over 16 contiguous nodes/warp; per-lane float4
// graph accumulators flushed on graph boundary (batch is sorted).
// =================================================================
__global__ void __launch_bounds__(256, 1)
pool_agg(const __nv_bfloat16* __restrict__ P,
         const float* __restrict__ partial,
         const int* __restrict__ batch,
         const float* __restrict__ fcW, const float* __restrict__ fcb,
         float* __restrict__ out) {
    int tid = threadIdx.x, lane = tid & 31, w = tid >> 5;
    int n0 = blockIdx.x * 128 + w * 16;

    float4 gacc = make_float4(0.f, 0.f, 0.f, 0.f);
    float cacc = 0.f;
    int gprev = -1;

    int nend = n0 + 16; if (nend > N_NODES) nend = N_NODES;
    for (int r = n0; r < nend; r++) {
        int g = batch[r];
        if (g != gprev) {
            if (gprev >= 0) {
                atomicAdd(&g_gsum[gprev * HID + lane * 4 + 0], gacc.x);
                atomicAdd(&g_gsum[gprev * HID + lane * 4 + 1], gacc.y);
                atomicAdd(&g_gsum[gprev * HID + lane * 4 + 2], gacc.z);
                atomicAdd(&g_gsum[gprev * HID + lane * 4 + 3], gacc.w);
                if (lane == 0) atomicAdd(&g_gcnt[gprev], cacc);
                gacc = make_float4(0.f, 0.f, 0.f, 0.f);
                cacc = 0.f;
            }
            gprev = g;
        }
        float4 o = agg_node(P, partial, r, lane);
        gacc.x += o.x; gacc.y += o.y; gacc.z += o.z; gacc.w += o.w;
        cacc += 1.f;
    }
    if (gprev >= 0) {
        atomicAdd(&g_gsum[gprev * HID + lane * 4 + 0], gacc.x);
        atomicAdd(&g_gsum[gprev * HID + lane * 4 + 1], gacc.y);
        atomicAdd(&g_gsum[gprev * HID + lane * 4 + 2], gacc.z);
        atomicAdd(&g_gsum[gprev * HID + lane * 4 + 3], gacc.w);
        if (lane == 0) atomicAdd(&g_gcnt[gprev], cacc);
    }

    // ticket: last block computes the final fc
    __threadfence();
    __syncthreads();          // all threads' atomics issued before ticket
    __shared__ int s_last;
    if (tid == 0) s_last = (atomicAdd(&g_tick, 1) == (int)gridDim.x - 1);
    __syncthreads();
    if (s_last && tid < N_GRAPHS * D_OUT) {
        int g = tid / D_OUT, o = tid % D_OUT;
        float cnt = g_gcnt[g];
        float inv = 1.0f / fmaxf(cnt, 1.0f);
        float s = 0.0f;
        #pragma unroll 8
        for (int k = 0; k < HID; k++)
            s += g_gsum[g * HID + k] * fcW[o * HID + k];
        out[g * D_OUT + o] = s * inv + fcb[o];
    }
}

// ---------------- launch ----------------
extern "C" void kernel_launch(void* const* d_in, const int* in_sizes, int n_in,
                              void* d_out, int out_size) {
    const float* x    = (const float*)d_in[0];
    const float* Wl0  = (const float*)d_in[1];
    const float* bl0  = (const float*)d_in[2];
    const float* Wr0  = (const float*)d_in[3];
    const float* W1   = (const float*)d_in[4];
    const float* b1   = (const float*)d_in[5];
    const float* Wl1  = (const float*)d_in[6];
    const float* bl1  = (const float*)d_in[7];
    const float* Wr1  = (const float*)d_in[8];
    const float* fcW  = (const float*)d_in[9];
    const float* fcb  = (const float*)d_in[10];
    const int*   ei   = (const int*)d_in[11];     // int64 ref -> int32 harness
    const int*   batch= (const int*)d_in[12];
    float*       out  = (float*)d_out;

    const int* src = ei;
    const int* dst = ei + N_EDGES;

    void *pP = nullptr, *pP2 = nullptr, *pA = nullptr;
    cudaGetSymbolAddress(&pP,  g_P);
    cudaGetSymbolAddress(&pP2, g_P2);
    cudaGetSymbolAddress(&pA,  g_bufA);
    __nv_bfloat16* P  = (__nv_bfloat16*)pP;
    __nv_bfloat16* P2 = (__nv_bfloat16*)pP2;
    float* bufA = (float*)pA;

    const int SMEM_D = 3 * 16384 * sizeof(float);   // 196608
    cudaFuncSetAttribute(gemm_dual,      cudaFuncAttributeMaxDynamicSharedMemorySize, SMEM_D);
    cudaFuncSetAttribute(gemm_fused_agg, cudaFuncAttributeMaxDynamicSharedMemorySize, SMEM_D);

    // side stream + events, created ONCE on first (non-captured) call
    static cudaStream_t s2 = nullptr;
    static cudaEvent_t evFork = nullptr, evJoin = nullptr;
    if (s2 == nullptr) {
        cudaStreamCreateWithFlags(&s2, cudaStreamNonBlocking);
        cudaEventCreateWithFlags(&evFork, cudaEventDisableTiming);
        cudaEventCreateWithFlags(&evJoin, cudaEventDisableTiming);
    }

    int gemm_blocks = (N_NODES + 127) / 128;   // 391

    // fork: CSR build on s2, conv0 dual GEMM on main stream (independent)
    cudaEventRecord(evFork, 0);
    cudaStreamWaitEvent(s2, evFork, 0);

    zero_kernel<<<(N_NODES + 255) / 256, 256, 0, s2>>>();
    hist_kernel<<<(N_EDGES / 4 + 255) / 256, 256, 0, s2>>>(dst);
    scan1_kernel<<<SCAN_BLOCKS, 256, 0, s2>>>();

    // conv0 on main stream: partial = x@Wr0^T + bl0 -> bufA, P = bf16(x@Wl0^T)
    gemm_dual<<<gemm_blocks, 256, SMEM_D>>>(x, Wr0, Wl0, bl0, bufA, P, N_NODES);

    scan3m_kernel<<<SCAN_BLOCKS, 256, 0, s2>>>();
    fill_kernel<<<(N_EDGES / 4 + 255) / 256, 256, 0, s2>>>(src, dst);

    // join: fused kernel's prologue gather needs CSR + conv0 outputs
    cudaEventRecord(evJoin, s2);
    cudaStreamWaitEvent(0, evJoin, 0);

    // fused conv0-combine + lin1 + conv1:
    //   prologue combines (P, bufA) -> x1 in smem; h = relu(x1@W1^T+b1);
    //   partial = h@Wr1^T + bl1 -> bufA, messages = bf16(h@Wl1^T) -> P2
    gemm_fused_agg<<<gemm_blocks, 256, SMEM_D>>>(P, bufA, W1, b1, Wr1, Wl1, bl1,
                                                 bufA, P2, N_NODES);

    // fused conv1-combine + pool + final fc
    pool_agg<<<gemm_blocks, 256>>>(P2, bufA, batch, fcW, fcb, out);
}

// round 15
// speedup vs baseline: 1.1887x; 1.1887x over previous
#include <cuda_runtime.h>
#include <cuda_bf16.h>
#include <cstdint>

#define N_NODES 50000
#define N_EDGES 600000
#define HID     128
#define N_GRAPHS 32
#define D_OUT   3
#define SCAN_BLOCKS ((N_NODES + 255) / 256)   // 196

typedef unsigned long long u64;

// ---------------- scratch (device globals; no allocs) ----------------
__device__ int   g_cnt[N_NODES];
__device__ int   g_rowptr[N_NODES + 1];
__device__ int   g_cursor[N_NODES];
__device__ int   g_col[N_EDGES];
__device__ int   g_bsum[SCAN_BLOCKS];
__device__ int   g_tick;
__device__ __nv_bfloat16 g_P[(size_t)N_NODES * HID];   // messages (bf16)
__device__ __nv_bfloat16 g_Q[(size_t)N_NODES * HID];   // partials (bf16)
__device__ float g_bufA[(size_t)N_NODES * HID];        // x1 then h2 (fp32)
__device__ float g_gsum[N_GRAPHS * HID];
__device__ float g_gcnt[N_GRAPHS];

// ---------------- f32x2 helpers ----------------
__device__ __forceinline__ u64 pack_dup(float a) {
    u64 r;
    asm("mov.b64 %0, {%1,%1};" : "=l"(r) : "f"(a));
    return r;
}
__device__ __forceinline__ float2 unpack2(u64 v) {
    float2 r;
    asm("mov.b64 {%0,%1}, %2;" : "=f"(r.x), "=f"(r.y) : "l"(v));
    return r;
}
__device__ __forceinline__ void ffma2(u64& acc, u64 a, u64 b) {
    asm("fma.rn.f32x2 %0, %1, %2, %0;" : "+l"(acc) : "l"(a), "l"(b));
}

// ---- R7-proven staging helpers (256 threads) ----
__device__ __forceinline__ void stage_A(float* sIn, const float* __restrict__ A,
                                        int m0, int M, int lane, int sub) {
    #pragma unroll
    for (int it = 0; it < 16; it++) {
        int row = it * 8 + sub;
        int grow = m0 + row;
        float4 v = make_float4(0.f, 0.f, 0.f, 0.f);
        if (grow < M) v = *(const float4*)(A + (size_t)grow * 128 + lane * 4);
        *(float4*)(sIn + row * 128 + lane * 4) = v;
    }
}
// sW k-major, float4 XOR-swizzle: (k, c4) at k*128 + ((c4 ^ ((k>>2)&31))<<2)
__device__ __forceinline__ void stage_W(float* sW, const float* __restrict__ W,
                                        int lane, int sub) {
    #pragma unroll
    for (int it = 0; it < 16; it++) {
        int col = it * 8 + sub;
        int c4 = col >> 2, cl = col & 3;
        float4 v = *(const float4*)(W + col * 128 + (lane << 2));
        float vv[4] = {v.x, v.y, v.z, v.w};
        #pragma unroll
        for (int i = 0; i < 4; i++) {
            int k = (lane << 2) + i;     // (k>>2)&31 == lane
            sW[k * 128 + ((c4 ^ lane) << 2) + cl] = vv[i];
        }
    }
}

// ---- R7-proven FFMA2 k-loops (tx = tid&15 col-group, ty = tid>>4 row-group) ----
__device__ __forceinline__ void kloop_single(const float* sIn, const float* sW1,
                                             u64 acc1[8][4], int tx, int ty) {
    #pragma unroll 4
    for (int k = 0; k < 128; k++) {
        u64 a2[8];
        #pragma unroll
        for (int r = 0; r < 8; r++)
            a2[r] = pack_dup(sIn[(ty * 8 + r) * 128 + k]);
        int swz = (k >> 2) & 31;
        const float* w1r = sW1 + k * 128;
        ulonglong2 p0 = *(const ulonglong2*)(w1r + ((((tx << 1)    ) ^ swz) << 2));
        ulonglong2 p1 = *(const ulonglong2*)(w1r + ((((tx << 1) | 1) ^ swz) << 2));
        u64 b1v[4] = {p0.x, p0.y, p1.x, p1.y};
        #pragma unroll
        for (int r = 0; r < 8; r++)
            #pragma unroll
            for (int c = 0; c < 4; c++)
                ffma2(acc1[r][c], a2[r], b1v[c]);
    }
}
__device__ __forceinline__ void kloop_dual(const float* sIn, const float* sW1,
                                           const float* sW2,
                                           u64 acc1[8][4], u64 acc2[8][4],
                                           int tx, int ty) {
    #pragma unroll 4
    for (int k = 0; k < 128; k++) {
        u64 a2[8];
        #pragma unroll
        for (int r = 0; r < 8; r++)
            a2[r] = pack_dup(sIn[(ty * 8 + r) * 128 + k]);
        int swz = (k >> 2) & 31;
        const float* w1r = sW1 + k * 128;
        ulonglong2 p0 = *(const ulonglong2*)(w1r + ((((tx << 1)    ) ^ swz) << 2));
        ulonglong2 p1 = *(const ulonglong2*)(w1r + ((((tx << 1) | 1) ^ swz) << 2));
        u64 b1v[4] = {p0.x, p0.y, p1.x, p1.y};
        #pragma unroll
        for (int r = 0; r < 8; r++)
            #pragma unroll
            for (int c = 0; c < 4; c++)
                ffma2(acc1[r][c], a2[r], b1v[c]);
        const float* w2r = sW2 + k * 128;
        ulonglong2 q0 = *(const ulonglong2*)(w2r + ((((tx << 1)    ) ^ swz) << 2));
        ulonglong2 q1 = *(const ulonglong2*)(w2r + ((((tx << 1) | 1) ^ swz) << 2));
        u64 b2v[4] = {q0.x, q0.y, q1.x, q1.y};
        #pragma unroll
        for (int r = 0; r < 8; r++)
            #pragma unroll
            for (int c = 0; c < 4; c++)
                ffma2(acc2[r][c], a2[r], b2v[c]);
    }
}

// ---- dual epilogue: out1 bf16 (+bias), out2 bf16 ----
__device__ __forceinline__ void epi_dual(u64 acc1[8][4], u64 acc2[8][4],
                                         const float* __restrict__ bias,
                                         __nv_bfloat16* __restrict__ out1,
                                         __nv_bfloat16* __restrict__ out2,
                                         int m0, int M, int tx, int ty) {
    float bv[8];
    #pragma unroll
    for (int j = 0; j < 8; j++) bv[j] = bias[tx * 8 + j];
    #pragma unroll
    for (int r = 0; r < 8; r++) {
        int grow = m0 + ty * 8 + r;
        if (grow < M) {
            __nv_bfloat162 h1[4], h2[4];
            #pragma unroll
            for (int c = 0; c < 4; c++) {
                float2 v = unpack2(acc1[r][c]);
                h1[c] = __float22bfloat162_rn(
                    make_float2(v.x + bv[2 * c], v.y + bv[2 * c + 1]));
                float2 w = unpack2(acc2[r][c]);
                h2[c] = __float22bfloat162_rn(w);
            }
            uint4 pk1, pk2;
            pk1.x = *(uint32_t*)&h1[0]; pk1.y = *(uint32_t*)&h1[1];
            pk1.z = *(uint32_t*)&h1[2]; pk1.w = *(uint32_t*)&h1[3];
            pk2.x = *(uint32_t*)&h2[0]; pk2.y = *(uint32_t*)&h2[1];
            pk2.z = *(uint32_t*)&h2[2]; pk2.w = *(uint32_t*)&h2[3];
            *(uint4*)(out1 + (size_t)grow * 128 + tx * 8) = pk1;
            *(uint4*)(out2 + (size_t)grow * 128 + tx * 8) = pk2;
        }
    }
}

// =================================================================
// conv0 dual GEMM: out1 = bf16(A@W1^T+bias), out2 = bf16(A@W2^T)
// =================================================================
__global__ void __launch_bounds__(256, 1)
gemm_dual(const float* __restrict__ A,
          const float* __restrict__ W1, const float* __restrict__ W2,
          const float* __restrict__ bias,
          __nv_bfloat16* __restrict__ out1, __nv_bfloat16* __restrict__ out2,
          int M) {
    extern __shared__ float smem[];
    float* sIn = smem;
    float* sW1 = smem + 16384;
    float* sW2 = smem + 32768;

    int tid = threadIdx.x;
    int tx = tid & 15, ty = tid >> 4;
    int lane = tid & 31, sub = tid >> 5;
    int m0 = blockIdx.x * 128;

    stage_A(sIn, A, m0, M, lane, sub);
    stage_W(sW1, W1, lane, sub);
    stage_W(sW2, W2, lane, sub);
    __syncthreads();

    u64 acc1[8][4], acc2[8][4];
    #pragma unroll
    for (int r = 0; r < 8; r++)
        #pragma unroll
        for (int c = 0; c < 4; c++) { acc1[r][c] = 0ull; acc2[r][c] = 0ull; }

    kloop_dual(sIn, sW1, sW2, acc1, acc2, tx, ty);
    epi_dual(acc1, acc2, bias, out1, out2, m0, M, tx, ty);
}

// =================================================================
// fused lin1 + conv1:
//   phase 1: h = relu(A@W1^T + b1) -> sIn
//   phase 2: out1 = bf16(h@Wr^T + blr), out2 = bf16(h@Wl^T)
// =================================================================
__global__ void __launch_bounds__(256, 1)
gemm_fused(const float* __restrict__ A,
           const float* __restrict__ W1, const float* __restrict__ b1,
           const float* __restrict__ Wr, const float* __restrict__ Wl,
           const float* __restrict__ blr,
           __nv_bfloat16* __restrict__ out1, __nv_bfloat16* __restrict__ out2,
           int M) {
    extern __shared__ float smem[];
    float* sIn = smem;
    float* sW1 = smem + 16384;
    float* sW2 = smem + 32768;

    int tid = threadIdx.x;
    int tx = tid & 15, ty = tid >> 4;
    int lane = tid & 31, sub = tid >> 5;
    int m0 = blockIdx.x * 128;

    // ---- phase 1: lin1 ----
    stage_A(sIn, A, m0, M, lane, sub);
    stage_W(sW1, W1, lane, sub);
    __syncthreads();

    u64 acc1[8][4], acc2[8][4];
    #pragma unroll
    for (int r = 0; r < 8; r++)
        #pragma unroll
        for (int c = 0; c < 4; c++) acc1[r][c] = 0ull;

    kloop_single(sIn, sW1, acc1, tx, ty);
    __syncthreads();   // everyone's reads of sIn / sW1 complete

    // write h = relu(acc1 + b1) back into sIn (same row-major layout)
    {
        float bv1[8];
        #pragma unroll
        for (int j = 0; j < 8; j++) bv1[j] = b1[tx * 8 + j];
        #pragma unroll
        for (int r = 0; r < 8; r++) {
            float o[8];
            #pragma unroll
            for (int c = 0; c < 4; c++) {
                float2 v = unpack2(acc1[r][c]);
                o[2 * c]     = fmaxf(v.x + bv1[2 * c], 0.f);
                o[2 * c + 1] = fmaxf(v.y + bv1[2 * c + 1], 0.f);
            }
            float4* d = (float4*)(sIn + (ty * 8 + r) * 128 + tx * 8);
            d[0] = make_float4(o[0], o[1], o[2], o[3]);
            d[1] = make_float4(o[4], o[5], o[6], o[7]);
        }
    }
    stage_W(sW1, Wr, lane, sub);
    stage_W(sW2, Wl, lane, sub);
    __syncthreads();

    // ---- phase 2: conv1 dual from h ----
    #pragma unroll
    for (int r = 0; r < 8; r++)
        #pragma unroll
        for (int c = 0; c < 4; c++) { acc1[r][c] = 0ull; acc2[r][c] = 0ull; }

    kloop_dual(sIn, sW1, sW2, acc1, acc2, tx, ty);
    epi_dual(acc1, acc2, blr, out1, out2, m0, M, tx, ty);
}

// ---------------- CSR build ----------------
__global__ void zero_kernel() {
    int i = blockIdx.x * blockDim.x + threadIdx.x;
    if (i < N_NODES) g_cnt[i] = 0;
    if (i < N_GRAPHS * HID) g_gsum[i] = 0.0f;
    if (i < N_GRAPHS) g_gcnt[i] = 0.0f;
    if (i == 0) g_tick = 0;
}

__global__ void hist_kernel(const int* __restrict__ dst) {
    int e4 = blockIdx.x * blockDim.x + threadIdx.x;
    if (e4 < N_EDGES / 4) {
        int4 d = ((const int4*)dst)[e4];
        atomicAdd(&g_cnt[d.x], 1);
        atomicAdd(&g_cnt[d.y], 1);
        atomicAdd(&g_cnt[d.z], 1);
        atomicAdd(&g_cnt[d.w], 1);
    }
}

__global__ void scan1_kernel() {
    __shared__ int ws[8];
    int tid = threadIdx.x, lane = tid & 31, w = tid >> 5;
    int i = blockIdx.x * 256 + tid;
    int v = (i < N_NODES) ? g_cnt[i] : 0;
    #pragma unroll
    for (int off = 16; off > 0; off >>= 1)
        v += __shfl_down_sync(0xffffffffu, v, off);
    if (lane == 0) ws[w] = v;
    __syncthreads();
    if (tid == 0) {
        int s = 0;
        #pragma unroll
        for (int j = 0; j < 8; j++) s += ws[j];
        g_bsum[blockIdx.x] = s;
    }
}

__global__ void scan3m_kernel() {
    __shared__ int ws[8];
    __shared__ int s_boff;
    int tid = threadIdx.x, lane = tid & 31, w = tid >> 5;

    int v = (tid < SCAN_BLOCKS) ? g_bsum[tid] : 0;
    int x = v;
    #pragma unroll
    for (int off = 1; off < 32; off <<= 1) {
        int t = __shfl_up_sync(0xffffffffu, x, off);
        if (lane >= off) x += t;
    }
    if (lane == 31) ws[w] = x;
    __syncthreads();
    if (w == 0 && lane < 8) {
        int y = ws[lane];
        #pragma unroll
        for (int off = 1; off < 8; off <<= 1) {
            int t = __shfl_up_sync(0xffu, y, off);
            if (lane >= off) y += t;
        }
        ws[lane] = y;
    }
    __syncthreads();
    int incl = x + (w > 0 ? ws[w - 1] : 0);
    if (tid == blockIdx.x) s_boff = incl - v;
    if (blockIdx.x == 0 && tid == 0) g_rowptr[0] = 0;
    __syncthreads();

    int i = blockIdx.x * 256 + tid;
    int c = (i < N_NODES) ? g_cnt[i] : 0;
    int y = c;
    #pragma unroll
    for (int off = 1; off < 32; off <<= 1) {
        int t = __shfl_up_sync(0xffffffffu, y, off);
        if (lane >= off) y += t;
    }
    if (lane == 31) ws[w] = y;
    __syncthreads();
    if (w == 0 && lane < 8) {
        int z = ws[lane];
        #pragma unroll
        for (int off = 1; off < 8; off <<= 1) {
            int t = __shfl_up_sync(0xffu, z, off);
            if (lane >= off) z += t;
        }
        ws[lane] = z;
    }
    __syncthreads();
    int inc2 = y + (w > 0 ? ws[w - 1] : 0) + s_boff;
    if (i < N_NODES) {
        g_rowptr[i + 1] = inc2;
        g_cursor[i] = inc2 - c;
    }
}

__global__ void fill_kernel(const int* __restrict__ src,
                            const int* __restrict__ dst) {
    int e4 = blockIdx.x * blockDim.x + threadIdx.x;
    if (e4 < N_EDGES / 4) {
        int4 d = ((const int4*)dst)[e4];
        int4 s = ((const int4*)src)[e4];
        g_col[atomicAdd(&g_cursor[d.x], 1)] = s.x;
        g_col[atomicAdd(&g_cursor[d.y], 1)] = s.y;
        g_col[atomicAdd(&g_cursor[d.z], 1)] = s.z;
        g_col[atomicAdd(&g_cursor[d.w], 1)] = s.w;
    }
}

// ------- fused aggregation: out = relu(partial + mean_{j in N(i)} P_j) -------
// warp per node; P and partial are bf16 (256B rows), out fp32.
__global__ void aggf_kernel(const __nv_bfloat16* __restrict__ P,
                            const __nv_bfloat16* __restrict__ partial,
                            float* __restrict__ out) {
    int node = (blockIdx.x * blockDim.x + threadIdx.x) >> 5;
    int lane = threadIdx.x & 31;
    if (node >= N_NODES) return;
    int s = g_rowptr[node];
    int e = g_rowptr[node + 1];
    float4 acc = make_float4(0.f, 0.f, 0.f, 0.f);
    for (int j = s; j < e; j++) {
        int sn = g_col[j];
        uint2 v = *((const uint2*)(P + (size_t)sn * HID) + lane);
        float2 f0 = __bfloat1622float2(*reinterpret_cast<__nv_bfloat162*>(&v.x));
        float2 f1 = __bfloat1622float2(*reinterpret_cast<__nv_bfloat162*>(&v.y));
        acc.x += f0.x; acc.y += f0.y; acc.z += f1.x; acc.w += f1.y;
    }
    int deg = e - s;
    float inv = 1.0f / (float)(deg > 0 ? deg : 1);
    uint2 pw = *((const uint2*)(partial + (size_t)node * HID) + lane);
    float2 pa = __bfloat1622float2(*reinterpret_cast<__nv_bfloat162*>(&pw.x));
    float2 pb = __bfloat1622float2(*reinterpret_cast<__nv_bfloat162*>(&pw.y));
    float4 o;
    o.x = fmaxf(pa.x + acc.x * inv, 0.f);
    o.y = fmaxf(pa.y + acc.y * inv, 0.f);
    o.z = fmaxf(pb.x + acc.z * inv, 0.f);
    o.w = fmaxf(pb.y + acc.w * inv, 0.f);
    *(float4*)(out + (size_t)node * HID + lane * 4) = o;
}

// ---------------- pooling + fused final (ticketed last block) ----------------
__global__ void pool_kernel(const float* __restrict__ h,
                            const int* __restrict__ batch,
                            const float* __restrict__ fcW,
                            const float* __restrict__ fcb,
                            float* __restrict__ out) {
    int t = threadIdx.x;
    int r0 = blockIdx.x * 128;
    int r1 = r0 + 128; if (r1 > N_NODES) r1 = N_NODES;
    if (r0 < N_NODES) {
        int gprev = batch[r0];
        float acc = 0.0f, cacc = 0.0f;
        for (int r = r0; r < r1; r++) {
            int g = batch[r];
            if (g != gprev) {
                atomicAdd(&g_gsum[gprev * HID + t], acc);
                if (t == 0) atomicAdd(&g_gcnt[gprev], cacc);
                acc = 0.0f; cacc = 0.0f; gprev = g;
            }
            acc += h[(size_t)r * HID + t];
            cacc += 1.0f;
        }
        atomicAdd(&g_gsum[gprev * HID + t], acc);
        if (t == 0) atomicAdd(&g_gcnt[gprev], cacc);
    }
    __syncthreads();          // all threads' atomics issued
    __threadfence();
    __shared__ int s_last;
    if (t == 0) s_last = (atomicAdd(&g_tick, 1) == (int)gridDim.x - 1);
    __syncthreads();
    if (s_last && t < N_GRAPHS * D_OUT) {
        int g = t / D_OUT, o = t % D_OUT;
        float cnt = g_gcnt[g];
        float inv = 1.0f / fmaxf(cnt, 1.0f);
        float s = 0.0f;
        #pragma unroll 8
        for (int k = 0; k < HID; k++)
            s += g_gsum[g * HID + k] * fcW[o * HID + k];
        out[g * D_OUT + o] = s * inv + fcb[o];
    }
}

// ---------------- launch ----------------
extern "C" void kernel_launch(void* const* d_in, const int* in_sizes, int n_in,
                              void* d_out, int out_size) {
    const float* x    = (const float*)d_in[0];
    const float* Wl0  = (const float*)d_in[1];
    const float* bl0  = (const float*)d_in[2];
    const float* Wr0  = (const float*)d_in[3];
    const float* W1   = (const float*)d_in[4];
    const float* b1   = (const float*)d_in[5];
    const float* Wl1  = (const float*)d_in[6];
    const float* bl1  = (const float*)d_in[7];
    const float* Wr1  = (const float*)d_in[8];
    const float* fcW  = (const float*)d_in[9];
    const float* fcb  = (const float*)d_in[10];
    const int*   ei   = (const int*)d_in[11];     // int64 ref -> int32 harness
    const int*   batch= (const int*)d_in[12];
    float*       out  = (float*)d_out;

    const int* src = ei;
    const int* dst = ei + N_EDGES;

    void *pP = nullptr, *pQ = nullptr, *pA = nullptr;
    cudaGetSymbolAddress(&pP, g_P);
    cudaGetSymbolAddress(&pQ, g_Q);
    cudaGetSymbolAddress(&pA, g_bufA);
    __nv_bfloat16* P = (__nv_bfloat16*)pP;
    __nv_bfloat16* Q = (__nv_bfloat16*)pQ;
    float* bufA = (float*)pA;

    const int SMEM_D = 3 * 16384 * sizeof(float);   // 196608
    cudaFuncSetAttribute(gemm_dual,  cudaFuncAttributeMaxDynamicSharedMemorySize, SMEM_D);
    cudaFuncSetAttribute(gemm_fused, cudaFuncAttributeMaxDynamicSharedMemorySize, SMEM_D);

    // side stream + events, created ONCE on first (non-captured) call
    static cudaStream_t s2 = nullptr;
    static cudaEvent_t evFork = nullptr, evJoin = nullptr;
    if (s2 == nullptr) {
        cudaStreamCreateWithFlags(&s2, cudaStreamNonBlocking);
        cudaEventCreateWithFlags(&evFork, cudaEventDisableTiming);
        cudaEventCreateWithFlags(&evJoin, cudaEventDisableTiming);
    }

    int gemm_blocks = (N_NODES + 127) / 128;   // 391

    // fork: CSR build on s2, conv0 dual GEMM on main stream (independent)
    cudaEventRecord(evFork, 0);
    cudaStreamWaitEvent(s2, evFork, 0);

    zero_kernel<<<(N_NODES + 255) / 256, 256, 0, s2>>>();
    hist_kernel<<<(N_EDGES / 4 + 255) / 256, 256, 0, s2>>>(dst);
    scan1_kernel<<<SCAN_BLOCKS, 256, 0, s2>>>();

    // conv0 on main stream: partial = bf16(x@Wr0^T + bl0) -> Q, P = bf16(x@Wl0^T)
    gemm_dual<<<gemm_blocks, 256, SMEM_D>>>(x, Wr0, Wl0, bl0, Q, P, N_NODES);

    scan3m_kernel<<<SCAN_BLOCKS, 256, 0, s2>>>();
    fill_kernel<<<(N_EDGES / 4 + 255) / 256, 256, 0, s2>>>(src, dst);

    // join: aggf needs CSR + conv0 outputs
    cudaEventRecord(evJoin, s2);
    cudaStreamWaitEvent(0, evJoin, 0);

    // conv0 combine: bufA = relu(Q + agg(P))   (x1, fp32)
    aggf_kernel<<<(N_NODES + 7) / 8, 256>>>(P, Q, bufA);

    // fused lin1+conv1: h = relu(bufA@W1^T+b1) (in smem);
    // partial = bf16(h@Wr1^T + bl1) -> Q, messages = bf16(h@Wl1^T) -> P
    gemm_fused<<<gemm_blocks, 256, SMEM_D>>>(bufA, W1, b1, Wr1, Wl1, bl1, Q, P, N_NODES);

    // conv1 combine: bufA = relu(Q + agg(P))   (h2, fp32; safe reuse)
    aggf_kernel<<<(N_NODES + 7) / 8, 256>>>(P, Q, bufA);

    // pool + fused final (ticketed)
    pool_kernel<<<(N_NODES + 127) / 128, 128>>>(bufA, batch, fcW, fcb, out);
}

// round 16
// speedup vs baseline: 1.2210x; 1.0271x over previous
#include <cuda_runtime.h>
#include <cuda_bf16.h>
#include <cstdint>

#define N_NODES 50000
#define N_EDGES 600000
#define HID     128
#define N_GRAPHS 32
#define D_OUT   3
#define SCAN_BLOCKS ((N_NODES + 255) / 256)   // 196

typedef unsigned long long u64;

// ---------------- scratch (device globals; no allocs) ----------------
__device__ int   g_cnt[N_NODES];
__device__ int   g_rowptr[N_NODES + 1];
__device__ int   g_cursor[N_NODES];
__device__ int   g_col[N_EDGES];
__device__ int   g_bsum[SCAN_BLOCKS];
__device__ int   g_tick;
__device__ __nv_bfloat16 g_P[(size_t)N_NODES * HID];   // messages (bf16)
__device__ __nv_bfloat16 g_Q[(size_t)N_NODES * HID];   // partials (bf16)
__device__ __nv_bfloat16 g_H2[(size_t)N_NODES * HID];  // h2 (bf16)
__device__ float g_bufA[(size_t)N_NODES * HID];        // x1 (fp32)
__device__ float g_gsum[N_GRAPHS * HID];
__device__ float g_gcnt[N_GRAPHS];

// ---------------- f32x2 helpers ----------------
__device__ __forceinline__ u64 pack_dup(float a) {
    u64 r;
    asm("mov.b64 %0, {%1,%1};" : "=l"(r) : "f"(a));
    return r;
}
__device__ __forceinline__ float2 unpack2(u64 v) {
    float2 r;
    asm("mov.b64 {%0,%1}, %2;" : "=f"(r.x), "=f"(r.y) : "l"(v));
    return r;
}
__device__ __forceinline__ void ffma2(u64& acc, u64 a, u64 b) {
    asm("fma.rn.f32x2 %0, %1, %2, %0;" : "+l"(acc) : "l"(a), "l"(b));
}

// ---- R7-proven staging helpers (256 threads) ----
__device__ __forceinline__ void stage_A(float* sIn, const float* __restrict__ A,
                                        int m0, int M, int lane, int sub) {
    #pragma unroll
    for (int it = 0; it < 16; it++) {
        int row = it * 8 + sub;
        int grow = m0 + row;
        float4 v = make_float4(0.f, 0.f, 0.f, 0.f);
        if (grow < M) v = *(const float4*)(A + (size_t)grow * 128 + lane * 4);
        *(float4*)(sIn + row * 128 + lane * 4) = v;
    }
}
// sW k-major, float4 XOR-swizzle: (k, c4) at k*128 + ((c4 ^ ((k>>2)&31))<<2)
__device__ __forceinline__ void stage_W(float* sW, const float* __restrict__ W,
                                        int lane, int sub) {
    #pragma unroll
    for (int it = 0; it < 16; it++) {
        int col = it * 8 + sub;
        int c4 = col >> 2, cl = col & 3;
        float4 v = *(const float4*)(W + col * 128 + (lane << 2));
        float vv[4] = {v.x, v.y, v.z, v.w};
        #pragma unroll
        for (int i = 0; i < 4; i++) {
            int k = (lane << 2) + i;     // (k>>2)&31 == lane
            sW[k * 128 + ((c4 ^ lane) << 2) + cl] = vv[i];
        }
    }
}

// ---- R7-proven FFMA2 k-loops (tx = tid&15 col-group, ty = tid>>4 row-group) ----
__device__ __forceinline__ void kloop_single(const float* sIn, const float* sW1,
                                             u64 acc1[8][4], int tx, int ty) {
    #pragma unroll 4
    for (int k = 0; k < 128; k++) {
        u64 a2[8];
        #pragma unroll
        for (int r = 0; r < 8; r++)
            a2[r] = pack_dup(sIn[(ty * 8 + r) * 128 + k]);
        int swz = (k >> 2) & 31;
        const float* w1r = sW1 + k * 128;
        ulonglong2 p0 = *(const ulonglong2*)(w1r + ((((tx << 1)    ) ^ swz) << 2));
        ulonglong2 p1 = *(const ulonglong2*)(w1r + ((((tx << 1) | 1) ^ swz) << 2));
        u64 b1v[4] = {p0.x, p0.y, p1.x, p1.y};
        #pragma unroll
        for (int r = 0; r < 8; r++)
            #pragma unroll
            for (int c = 0; c < 4; c++)
                ffma2(acc1[r][c], a2[r], b1v[c]);
    }
}
__device__ __forceinline__ void kloop_dual(const float* sIn, const float* sW1,
                                           const float* sW2,
                                           u64 acc1[8][4], u64 acc2[8][4],
                                           int tx, int ty) {
    #pragma unroll 4
    for (int k = 0; k < 128; k++) {
        u64 a2[8];
        #pragma unroll
        for (int r = 0; r < 8; r++)
            a2[r] = pack_dup(sIn[(ty * 8 + r) * 128 + k]);
        int swz = (k >> 2) & 31;
        const float* w1r = sW1 + k * 128;
        ulonglong2 p0 = *(const ulonglong2*)(w1r + ((((tx << 1)    ) ^ swz) << 2));
        ulonglong2 p1 = *(const ulonglong2*)(w1r + ((((tx << 1) | 1) ^ swz) << 2));
        u64 b1v[4] = {p0.x, p0.y, p1.x, p1.y};
        #pragma unroll
        for (int r = 0; r < 8; r++)
            #pragma unroll
            for (int c = 0; c < 4; c++)
                ffma2(acc1[r][c], a2[r], b1v[c]);
        const float* w2r = sW2 + k * 128;
        ulonglong2 q0 = *(const ulonglong2*)(w2r + ((((tx << 1)    ) ^ swz) << 2));
        ulonglong2 q1 = *(const ulonglong2*)(w2r + ((((tx << 1) | 1) ^ swz) << 2));
        u64 b2v[4] = {q0.x, q0.y, q1.x, q1.y};
        #pragma unroll
        for (int r = 0; r < 8; r++)
            #pragma unroll
            for (int c = 0; c < 4; c++)
                ffma2(acc2[r][c], a2[r], b2v[c]);
    }
}

// ---- dual epilogue: out1 bf16 (+bias), out2 bf16 ----
__device__ __forceinline__ void epi_dual(u64 acc1[8][4], u64 acc2[8][4],
                                         const float* __restrict__ bias,
                                         __nv_bfloat16* __restrict__ out1,
                                         __nv_bfloat16* __restrict__ out2,
                                         int m0, int M, int tx, int ty) {
    float bv[8];
    #pragma unroll
    for (int j = 0; j < 8; j++) bv[j] = bias[tx * 8 + j];
    #pragma unroll
    for (int r = 0; r < 8; r++) {
        int grow = m0 + ty * 8 + r;
        if (grow < M) {
            __nv_bfloat162 h1[4], h2[4];
            #pragma unroll
            for (int c = 0; c < 4; c++) {
                float2 v = unpack2(acc1[r][c]);
                h1[c] = __float22bfloat162_rn(
                    make_float2(v.x + bv[2 * c], v.y + bv[2 * c + 1]));
                float2 w = unpack2(acc2[r][c]);
                h2[c] = __float22bfloat162_rn(w);
            }
            uint4 pk1, pk2;
            pk1.x = *(uint32_t*)&h1[0]; pk1.y = *(uint32_t*)&h1[1];
            pk1.z = *(uint32_t*)&h1[2]; pk1.w = *(uint32_t*)&h1[3];
            pk2.x = *(uint32_t*)&h2[0]; pk2.y = *(uint32_t*)&h2[1];
            pk2.z = *(uint32_t*)&h2[2]; pk2.w = *(uint32_t*)&h2[3];
            *(uint4*)(out1 + (size_t)grow * 128 + tx * 8) = pk1;
            *(uint4*)(out2 + (size_t)grow * 128 + tx * 8) = pk2;
        }
    }
}

// =================================================================
// conv0 dual GEMM, PERSISTENT: weights staged once, loop over tiles.
// out1 = bf16(A@W1^T+bias), out2 = bf16(A@W2^T)
// =================================================================
__global__ void __launch_bounds__(256, 1)
gemm_dual(const float* __restrict__ A,
          const float* __restrict__ W1, const float* __restrict__ W2,
          const float* __restrict__ bias,
          __nv_bfloat16* __restrict__ out1, __nv_bfloat16* __restrict__ out2,
          int M) {
    extern __shared__ float smem[];
    float* sIn = smem;
    float* sW1 = smem + 16384;
    float* sW2 = smem + 32768;

    int tid = threadIdx.x;
    int tx = tid & 15, ty = tid >> 4;
    int lane = tid & 31, sub = tid >> 5;

    stage_W(sW1, W1, lane, sub);
    stage_W(sW2, W2, lane, sub);

    int ntiles = (M + 127) >> 7;
    for (int t = blockIdx.x; t < ntiles; t += gridDim.x) {
        int m0 = t << 7;
        __syncthreads();              // prev kloop reads done / W staged
        stage_A(sIn, A, m0, M, lane, sub);
        __syncthreads();

        u64 acc1[8][4], acc2[8][4];
        #pragma unroll
        for (int r = 0; r < 8; r++)
            #pragma unroll
            for (int c = 0; c < 4; c++) { acc1[r][c] = 0ull; acc2[r][c] = 0ull; }

        kloop_dual(sIn, sW1, sW2, acc1, acc2, tx, ty);
        epi_dual(acc1, acc2, bias, out1, out2, m0, M, tx, ty);
    }
}

// =================================================================
// fused lin1 + conv1 (early-Wl staging):
//   phase 1: h = relu(A@W1^T + b1) -> sIn   (Wl already staged in sW2)
//   phase 2: out1 = bf16(h@Wr^T + blr), out2 = bf16(h@Wl^T)
// =================================================================
__global__ void __launch_bounds__(256, 1)
gemm_fused(const float* __restrict__ A,
           const float* __restrict__ W1, const float* __restrict__ b1,
           const float* __restrict__ Wr, const float* __restrict__ Wl,
           const float* __restrict__ blr,
           __nv_bfloat16* __restrict__ out1, __nv_bfloat16* __restrict__ out2,
           int M) {
    extern __shared__ float smem[];
    float* sIn = smem;
    float* sW1 = smem + 16384;
    float* sW2 = smem + 32768;

    int tid = threadIdx.x;
    int tx = tid & 15, ty = tid >> 4;
    int lane = tid & 31, sub = tid >> 5;
    int m0 = blockIdx.x * 128;

    // ---- phase 1: lin1 (stage Wl early into the idle sW2) ----
    stage_A(sIn, A, m0, M, lane, sub);
    stage_W(sW1, W1, lane, sub);
    stage_W(sW2, Wl, lane, sub);
    __syncthreads();

    u64 acc1[8][4], acc2[8][4];
    #pragma unroll
    for (int r = 0; r < 8; r++)
        #pragma unroll
        for (int c = 0; c < 4; c++) acc1[r][c] = 0ull;

    kloop_single(sIn, sW1, acc1, tx, ty);
    __syncthreads();   // everyone's reads of sIn / sW1 complete

    // write h = relu(acc1 + b1) back into sIn (same row-major layout)
    {
        float bv1[8];
        #pragma unroll
        for (int j = 0; j < 8; j++) bv1[j] = b1[tx * 8 + j];
        #pragma unroll
        for (int r = 0; r < 8; r++) {
            float o[8];
            #pragma unroll
            for (int c = 0; c < 4; c++) {
                float2 v = unpack2(acc1[r][c]);
                o[2 * c]     = fmaxf(v.x + bv1[2 * c], 0.f);
                o[2 * c + 1] = fmaxf(v.y + bv1[2 * c + 1], 0.f);
            }
            float4* d = (float4*)(sIn + (ty * 8 + r) * 128 + tx * 8);
            d[0] = make_float4(o[0], o[1], o[2], o[3]);
            d[1] = make_float4(o[4], o[5], o[6], o[7]);
        }
    }
    stage_W(sW1, Wr, lane, sub);   // only Wr staged mid-kernel now
    __syncthreads();

    // ---- phase 2: conv1 dual from h ----
    #pragma unroll
    for (int r = 0; r < 8; r++)
        #pragma unroll
        for (int c = 0; c < 4; c++) { acc1[r][c] = 0ull; acc2[r][c] = 0ull; }

    kloop_dual(sIn, sW1, sW2, acc1, acc2, tx, ty);
    epi_dual(acc1, acc2, blr, out1, out2, m0, M, tx, ty);
}

// ---------------- CSR build ----------------
__global__ void zero_kernel() {
    int i = blockIdx.x * blockDim.x + threadIdx.x;
    if (i < N_NODES) g_cnt[i] = 0;
    if (i < N_GRAPHS * HID) g_gsum[i] = 0.0f;
    if (i < N_GRAPHS) g_gcnt[i] = 0.0f;
    if (i == 0) g_tick = 0;
}

__global__ void hist_kernel(const int* __restrict__ dst) {
    int e4 = blockIdx.x * blockDim.x + threadIdx.x;
    if (e4 < N_EDGES / 4) {
        int4 d = ((const int4*)dst)[e4];
        atomicAdd(&g_cnt[d.x], 1);
        atomicAdd(&g_cnt[d.y], 1);
        atomicAdd(&g_cnt[d.z], 1);
        atomicAdd(&g_cnt[d.w], 1);
    }
}

__global__ void scan1_kernel() {
    __shared__ int ws[8];
    int tid = threadIdx.x, lane = tid & 31, w = tid >> 5;
    int i = blockIdx.x * 256 + tid;
    int v = (i < N_NODES) ? g_cnt[i] : 0;
    #pragma unroll
    for (int off = 16; off > 0; off >>= 1)
        v += __shfl_down_sync(0xffffffffu, v, off);
    if (lane == 0) ws[w] = v;
    __syncthreads();
    if (tid == 0) {
        int s = 0;
        #pragma unroll
        for (int j = 0; j < 8; j++) s += ws[j];
        g_bsum[blockIdx.x] = s;
    }
}

__global__ void scan3m_kernel() {
    __shared__ int ws[8];
    __shared__ int s_boff;
    int tid = threadIdx.x, lane = tid & 31, w = tid >> 5;

    int v = (tid < SCAN_BLOCKS) ? g_bsum[tid] : 0;
    int x = v;
    #pragma unroll
    for (int off = 1; off < 32; off <<= 1) {
        int t = __shfl_up_sync(0xffffffffu, x, off);
        if (lane >= off) x += t;
    }
    if (lane == 31) ws[w] = x;
    __syncthreads();
    if (w == 0 && lane < 8) {
        int y = ws[lane];
        #pragma unroll
        for (int off = 1; off < 8; off <<= 1) {
            int t = __shfl_up_sync(0xffu, y, off);
            if (lane >= off) y += t;
        }
        ws[lane] = y;
    }
    __syncthreads();
    int incl = x + (w > 0 ? ws[w - 1] : 0);
    if (tid == blockIdx.x) s_boff = incl - v;
    if (blockIdx.x == 0 && tid == 0) g_rowptr[0] = 0;
    __syncthreads();

    int i = blockIdx.x * 256 + tid;
    int c = (i < N_NODES) ? g_cnt[i] : 0;
    int y = c;
    #pragma unroll
    for (int off = 1; off < 32; off <<= 1) {
        int t = __shfl_up_sync(0xffffffffu, y, off);
        if (lane >= off) y += t;
    }
    if (lane == 31) ws[w] = y;
    __syncthreads();
    if (w == 0 && lane < 8) {
        int z = ws[lane];
        #pragma unroll
        for (int off = 1; off < 8; off <<= 1) {
            int t = __shfl_up_sync(0xffu, z, off);
            if (lane >= off) z += t;
        }
        ws[lane] = z;
    }
    __syncthreads();
    int inc2 = y + (w > 0 ? ws[w - 1] : 0) + s_boff;
    if (i < N_NODES) {
        g_rowptr[i + 1] = inc2;
        g_cursor[i] = inc2 - c;
    }
}

__global__ void fill_kernel(const int* __restrict__ src,
                            const int* __restrict__ dst) {
    int e4 = blockIdx.x * blockDim.x + threadIdx.x;
    if (e4 < N_EDGES / 4) {
        int4 d = ((const int4*)dst)[e4];
        int4 s = ((const int4*)src)[e4];
        g_col[atomicAdd(&g_cursor[d.x], 1)] = s.x;
        g_col[atomicAdd(&g_cursor[d.y], 1)] = s.y;
        g_col[atomicAdd(&g_cursor[d.z], 1)] = s.z;
        g_col[atomicAdd(&g_cursor[d.w], 1)] = s.w;
    }
}

// ---- shared gather core: acc = sum_{nbr} P[nbr], o = relu(Q[node] + acc/deg)
__device__ __forceinline__ float4 agg_core(const __nv_bfloat16* __restrict__ P,
                                           const __nv_bfloat16* __restrict__ Q,
                                           int node, int lane) {
    int s = g_rowptr[node];
    int e = g_rowptr[node + 1];
    float4 acc = make_float4(0.f, 0.f, 0.f, 0.f);
    for (int j = s; j < e; j++) {
        int sn = g_col[j];
        uint2 v = *((const uint2*)(P + (size_t)sn * HID) + lane);
        float2 f0 = __bfloat1622float2(*reinterpret_cast<__nv_bfloat162*>(&v.x));
        float2 f1 = __bfloat1622float2(*reinterpret_cast<__nv_bfloat162*>(&v.y));
        acc.x += f0.x; acc.y += f0.y; acc.z += f1.x; acc.w += f1.y;
    }
    int deg = e - s;
    float inv = 1.0f / (float)(deg > 0 ? deg : 1);
    uint2 pw = *((const uint2*)(Q + (size_t)node * HID) + lane);
    float2 pa = __bfloat1622float2(*reinterpret_cast<__nv_bfloat162*>(&pw.x));
    float2 pb = __bfloat1622float2(*reinterpret_cast<__nv_bfloat162*>(&pw.y));
    float4 o;
    o.x = fmaxf(pa.x + acc.x * inv, 0.f);
    o.y = fmaxf(pa.y + acc.y * inv, 0.f);
    o.z = fmaxf(pb.x + acc.z * inv, 0.f);
    o.w = fmaxf(pb.y + acc.w * inv, 0.f);
    return o;
}

// conv0 combine -> fp32 (feeds GEMM staging)
__global__ void aggf_f32(const __nv_bfloat16* __restrict__ P,
                         const __nv_bfloat16* __restrict__ Q,
                         float* __restrict__ out) {
    int node = (blockIdx.x * blockDim.x + threadIdx.x) >> 5;
    int lane = threadIdx.x & 31;
    if (node >= N_NODES) return;
    float4 o = agg_core(P, Q, node, lane);
    *(float4*)(out + (size_t)node * HID + lane * 4) = o;
}

// conv1 combine -> bf16 (feeds pool)
__global__ void aggf_bf16(const __nv_bfloat16* __restrict__ P,
                          const __nv_bfloat16* __restrict__ Q,
                          __nv_bfloat16* __restrict__ out) {
    int node = (blockIdx.x * blockDim.x + threadIdx.x) >> 5;
    int lane = threadIdx.x & 31;
    if (node >= N_NODES) return;
    float4 o = agg_core(P, Q, node, lane);
    __nv_bfloat162 h0 = __float22bfloat162_rn(make_float2(o.x, o.y));
    __nv_bfloat162 h1 = __float22bfloat162_rn(make_float2(o.z, o.w));
    uint2 pk;
    pk.x = *(uint32_t*)&h0;
    pk.y = *(uint32_t*)&h1;
    *((uint2*)(out + (size_t)node * HID) + lane) = pk;
}

// ---------------- pooling (bf16 input) + fused final (ticketed) ----------------
__global__ void pool_kernel(const __nv_bfloat16* __restrict__ h,
                            const int* __restrict__ batch,
                            const float* __restrict__ fcW,
                            const float* __restrict__ fcb,
                            float* __restrict__ out) {
    int t = threadIdx.x;
    int r0 = blockIdx.x * 128;
    int r1 = r0 + 128; if (r1 > N_NODES) r1 = N_NODES;
    if (r0 < N_NODES) {
        int gprev = batch[r0];
        float acc = 0.0f, cacc = 0.0f;
        for (int r = r0; r < r1; r++) {
            int g = batch[r];
            if (g != gprev) {
                atomicAdd(&g_gsum[gprev * HID + t], acc);
                if (t == 0) atomicAdd(&g_gcnt[gprev], cacc);
                acc = 0.0f; cacc = 0.0f; gprev = g;
            }
            acc += __bfloat162float(h[(size_t)r * HID + t]);
            cacc += 1.0f;
        }
        atomicAdd(&g_gsum[gprev * HID + t], acc);
        if (t == 0) atomicAdd(&g_gcnt[gprev], cacc);
    }
    __syncthreads();          // all threads' atomics issued
    __threadfence();
    __shared__ int s_last;
    if (t == 0) s_last = (atomicAdd(&g_tick, 1) == (int)gridDim.x - 1);
    __syncthreads();
    if (s_last && t < N_GRAPHS * D_OUT) {
        int g = t / D_OUT, o = t % D_OUT;
        float cnt = g_gcnt[g];
        float inv = 1.0f / fmaxf(cnt, 1.0f);
        float s = 0.0f;
        #pragma unroll 8
        for (int k = 0; k < HID; k++)
            s += g_gsum[g * HID + k] * fcW[o * HID + k];
        out[g * D_OUT + o] = s * inv + fcb[o];
    }
}

// ---------------- launch ----------------
extern "C" void kernel_launch(void* const* d_in, const int* in_sizes, int n_in,
                              void* d_out, int out_size) {
    const float* x    = (const float*)d_in[0];
    const float* Wl0  = (const float*)d_in[1];
    const float* bl0  = (const float*)d_in[2];
    const float* Wr0  = (const float*)d_in[3];
    const float* W1   = (const float*)d_in[4];
    const float* b1   = (const float*)d_in[5];
    const float* Wl1  = (const float*)d_in[6];
    const float* bl1  = (const float*)d_in[7];
    const float* Wr1  = (const float*)d_in[8];
    const float* fcW  = (const float*)d_in[9];
    const float* fcb  = (const float*)d_in[10];
    const int*   ei   = (const int*)d_in[11];     // int64 ref -> int32 harness
    const int*   batch= (const int*)d_in[12];
    float*       out  = (float*)d_out;

    const int* src = ei;
    const int* dst = ei + N_EDGES;

    void *pP = nullptr, *pQ = nullptr, *pH = nullptr, *pA = nullptr;
    cudaGetSymbolAddress(&pP, g_P);
    cudaGetSymbolAddress(&pQ, g_Q);
    cudaGetSymbolAddress(&pH, g_H2);
    cudaGetSymbolAddress(&pA, g_bufA);
    __nv_bfloat16* P  = (__nv_bfloat16*)pP;
    __nv_bfloat16* Q  = (__nv_bfloat16*)pQ;
    __nv_bfloat16* H2 = (__nv_bfloat16*)pH;
    float* bufA = (float*)pA;

    const int SMEM_D = 3 * 16384 * sizeof(float);   // 196608
    cudaFuncSetAttribute(gemm_dual,  cudaFuncAttributeMaxDynamicSharedMemorySize, SMEM_D);
    cudaFuncSetAttribute(gemm_fused, cudaFuncAttributeMaxDynamicSharedMemorySize, SMEM_D);

    // side stream + events, created ONCE on first (non-captured) call
    static cudaStream_t s2 = nullptr;
    static cudaEvent_t evFork = nullptr, evJoin = nullptr;
    if (s2 == nullptr) {
        cudaStreamCreateWithFlags(&s2, cudaStreamNonBlocking);
        cudaEventCreateWithFlags(&evFork, cudaEventDisableTiming);
        cudaEventCreateWithFlags(&evJoin, cudaEventDisableTiming);
    }

    int gemm_blocks = (N_NODES + 127) / 128;   // 391

    // fork: CSR build on s2, conv0 dual GEMM on main stream (independent)
    cudaEventRecord(evFork, 0);
    cudaStreamWaitEvent(s2, evFork, 0);

    zero_kernel<<<(N_NODES + 255) / 256, 256, 0, s2>>>();
    hist_kernel<<<(N_EDGES / 4 + 255) / 256, 256, 0, s2>>>(dst);
    scan1_kernel<<<SCAN_BLOCKS, 256, 0, s2>>>();

    // conv0 on main stream (persistent; pos 4 for ncu):
    // partial = bf16(x@Wr0^T + bl0) -> Q, P = bf16(x@Wl0^T)
    gemm_dual<<<148, 256, SMEM_D>>>(x, Wr0, Wl0, bl0, Q, P, N_NODES);

    scan3m_kernel<<<SCAN_BLOCKS, 256, 0, s2>>>();
    fill_kernel<<<(N_EDGES / 4 + 255) / 256, 256, 0, s2>>>(src, dst);

    // join: aggf needs CSR + conv0 outputs
    cudaEventRecord(evJoin, s2);
    cudaStreamWaitEvent(0, evJoin, 0);

    // conv0 combine: bufA = relu(Q + agg(P))   (x1, fp32)
    aggf_f32<<<(N_NODES + 7) / 8, 256>>>(P, Q, bufA);

    // fused lin1+conv1: h = relu(bufA@W1^T+b1) (in smem);
    // partial = bf16(h@Wr1^T + bl1) -> Q, messages = bf16(h@Wl1^T) -> P
    gemm_fused<<<gemm_blocks, 256, SMEM_D>>>(bufA, W1, b1, Wr1, Wl1, bl1, Q, P, N_NODES);

    // conv1 combine: H2 = bf16(relu(Q + agg(P)))
    aggf_bf16<<<(N_NODES + 7) / 8, 256>>>(P, Q, H2);

    // pool + fused final (ticketed)
    pool_kernel<<<(N_NODES + 127) / 128, 128>>>(H2, batch, fcW, fcb, out);
}